// round 11
// baseline (speedup 1.0000x reference)
#include <cuda_runtime.h>
#include <cuda_fp16.h>

#define B_ 16
#define O_ 32
#define CPO_ 4
#define H_ 128
#define W_ 128
#define S_ 16
#define T_ 32
#define HW_ (H_*W_)
#define NT_ ((B_*O_*H_*W_/4)/256)   /* transpose blocks = 8192 */
#define ROW2_ (W_*4)                /* bytes per plane row = 512 */
#define KH_ 8

typedef unsigned long long ull;

// Scratch: 2-channel planes. Plane (bo*2+cp) is (H, W) of half2 (4B/pixel).
__device__ unsigned g_xP[(size_t)B_ * O_ * 2 * H_ * W_];
__device__ int2  g_shift[O_ * S_];
__device__ uint4 g_wtsh[O_ * S_];
// Zero page: OOB loads redirect here (fast path reads up to 8*512+8 bytes).
__device__ uint4 g_zero[4 * 64 + 8];   // 4224 B, zero-initialized

// ---------------------------------------------------------------------------
// packed helpers
// ---------------------------------------------------------------------------
__device__ __forceinline__ void add2(ull& d, ull v) {
    asm("add.rn.f32x2 %0,%0,%1;" : "+l"(d) : "l"(v));
}
__device__ __forceinline__ void unpk(ull v, float& lo, float& hi) {
    asm("mov.b64 {%0,%1},%2;" : "=f"(lo), "=f"(hi) : "l"(v));
}
__device__ __forceinline__ ull h2f2(unsigned u) {
    ull r;
    asm("{\n\t.reg .b16 a,b;\n\t.reg .f32 lo,hi;\n\t"
        "mov.b32 {a,b},%1;\n\tcvt.f32.f16 lo,a;\n\tcvt.f32.f16 hi,b;\n\t"
        "mov.b64 %0,{lo,hi};\n\t}" : "=l"(r) : "r"(u));
    return r;
}
__device__ __forceinline__ __half2 u2h(unsigned u) {
    return *reinterpret_cast<__half2*>(&u);
}
__device__ __forceinline__ unsigned h2u(__half2 h) {
    return *reinterpret_cast<unsigned*>(&h);
}

// ---------------------------------------------------------------------------
// Kernel 1 (fused): blocks [0,NT_) transpose, blocks [NT_,NT_+4) params.
// Transpose: (B,O,CPO,H,W) fp32 -> two half2 planes per (b,o):
//   plane(bo*2+0) = channels 0,1 ; plane(bo*2+1) = channels 2,3.
// ---------------------------------------------------------------------------
__global__ void pre_kernel(const float* __restrict__ x,
                           const float* __restrict__ ox, const float* __restrict__ oy,
                           const float* __restrict__ ua, const float* __restrict__ us,
                           const float* __restrict__ ar, const float* __restrict__ sr)
{
    if (blockIdx.x < NT_) {
        int idx  = blockIdx.x * 256 + threadIdx.x;      // pixel-group of 4
        int wg   = idx & (W_/4 - 1);
        int rest = idx >> 5;                            // bo*H + h
        int h    = rest & (H_ - 1);
        int bo   = rest >> 7;
        size_t base = ((size_t)bo * CPO_ * H_ + h) * W_ + wg * 4;

        float4 c0 = *(const float4*)(x + base);
        float4 c1 = *(const float4*)(x + base + HW_);
        float4 c2 = *(const float4*)(x + base + 2 * HW_);
        float4 c3 = *(const float4*)(x + base + 3 * HW_);

        uint4 o01, o23;
        __half2 h2v;
        h2v = __floats2half2_rn(c0.x, c1.x); o01.x = h2u(h2v);
        h2v = __floats2half2_rn(c0.y, c1.y); o01.y = h2u(h2v);
        h2v = __floats2half2_rn(c0.z, c1.z); o01.z = h2u(h2v);
        h2v = __floats2half2_rn(c0.w, c1.w); o01.w = h2u(h2v);
        h2v = __floats2half2_rn(c2.x, c3.x); o23.x = h2u(h2v);
        h2v = __floats2half2_rn(c2.y, c3.y); o23.y = h2u(h2v);
        h2v = __floats2half2_rn(c2.z, c3.z); o23.z = h2u(h2v);
        h2v = __floats2half2_rn(c2.w, c3.w); o23.w = h2u(h2v);

        size_t q = (((size_t)bo * 2) * HW_ + (size_t)h * W_) >> 2;  // uint4 units
        reinterpret_cast<uint4*>(g_xP)[q + wg] = o01;
        reinterpret_cast<uint4*>(g_xP)[q + (HW_ >> 2) + wg] = o23;
        return;
    }

    // ---- param path ----
    const int lane = threadIdx.x & 31;
    const int o    = (blockIdx.x - NT_) * 8 + (threadIdx.x >> 5);
    const float MINA = 0.024979197860971382f;
    const float PIF  = 3.14159265358979323846f;
    const float EPSF = 1.1920928955078125e-07f;

    float astd = 1.f / (1.f + expf(-ar[o])) * (PIF - MINA) + MINA;
    float sstd = 1.f / (1.f + expf(-sr[o])) * (5.0f - 0.2f) + 0.2f;
    float high_a = fminf(astd * 3.f, PIF);
    float s3 = sstd * 3.f;
    float ia  = 0.5f / (astd * astd + EPSF);
    float isc = 0.5f / (sstd * sstd + EPSF);

    float a = ua[o * T_ + lane] * high_a;
    float s = us[o * T_ + lane] * s3;
    float w = expf(-(a * a * ia + s * s * isc));
    float sum = w;
    #pragma unroll
    for (int d = 16; d; d >>= 1) sum += __shfl_xor_sync(0xffffffffu, sum, d);
    float inv = 2.f / (sum + EPSF);

    if (lane < S_) {
        float oxv = ox[o], oyv = oy[o];
        float dist = sqrtf(oxv * oxv + oyv * oyv);
        float a0 = atan2f(oyv, oxv);

        float ws = w * inv;
        float nd = dist + s;
        float na = a0 + a;
        float dx = nd * cosf(na);
        float dy = nd * sinf(na);
        float fy = floorf(dy), fx = floorf(dx);
        float ay = dy - fy,  axf = dx - fx;
        int iy = max(-H_, min(H_ - 1, (int)fy));
        int ix = max(-W_, min(W_ - 1, (int)fx));
        float wy0 = 1.f - ay, wx0 = 1.f - axf;
        int key = ((iy + 256) << 10) | (ix + 256);

        int rank = 0;
        #pragma unroll
        for (int j = 0; j < S_; j++) {
            int kj = __shfl_sync(0x0000ffffu, key, j);
            rank += (kj < key) || (kj == key && j < lane);
        }
        __half2 h00 = __float2half2_rn(ws * wy0 * wx0);
        __half2 h01 = __float2half2_rn(ws * wy0 * axf);
        __half2 h10 = __float2half2_rn(ws * ay * wx0);
        __half2 h11 = __float2half2_rn(ws * ay * axf);
        g_shift[o * S_ + rank] = make_int2(iy, ix);
        g_wtsh[o * S_ + rank]  = make_uint4(h2u(h00), h2u(h01), h2u(h10), h2u(h11));
    }
}

// ---------------------------------------------------------------------------
// Kernel 2: main gather.
// Block = 128 threads = 4 warps; warp = 8 output rows (KH=8) x 64 px x 2 ch.
// Lane owns 2 adjacent pixels of ONE channel-pair plane (4B/px).
// Per sample-row: 1 LDG.64 + 1 LDG.32 (12B = the 3 column slots), ~4 L1
// wavefronts per row; 9 rows amortized over 8 output rows (vs 5/4 before).
// Parity via block-uniform template; OOB redirect to zero page; rolling
// 2-row window. fp16 accumulates 4 samples, flushed to packed fp32x2.
// ---------------------------------------------------------------------------
struct Row3 { unsigned a, b, c; };

template<bool ODD>
__device__ __forceinline__ Row3 ldRow(const char* p1, const char* p2)
{
    Row3 r;
    if (ODD) {            // p1 -> col cl (uint), p2 -> cols cl+1, cl+2 (uint2)
        unsigned A = *(const unsigned*)p1;
        uint2    BC = *(const uint2*)p2;
        r.a = A; r.b = BC.x; r.c = BC.y;
    } else {              // p1 -> cols cl, cl+1 (uint2), p2 -> col cl+2 (uint)
        uint2    AB = *(const uint2*)p1;
        unsigned C = *(const unsigned*)p2;
        r.a = AB.x; r.b = AB.y; r.c = C;
    }
    return r;
}

template<bool FIRST>
__device__ __forceinline__ void tap_row(const Row3& Tr, const Row3& Ur,
                                        unsigned& h0, unsigned& h1,
                                        __half2 w00, __half2 w01, __half2 w10, __half2 w11)
{
    __half2 a;
    a = FIRST ? __hmul2(u2h(Tr.a), w00) : __hfma2(u2h(Tr.a), w00, u2h(h0));
    a = __hfma2(u2h(Tr.b), w01, a);
    a = __hfma2(u2h(Ur.a), w10, a);
    a = __hfma2(u2h(Ur.b), w11, a);
    h0 = h2u(a);
    a = FIRST ? __hmul2(u2h(Tr.b), w00) : __hfma2(u2h(Tr.b), w00, u2h(h1));
    a = __hfma2(u2h(Tr.c), w01, a);
    a = __hfma2(u2h(Ur.b), w10, a);
    a = __hfma2(u2h(Ur.c), w11, a);
    h1 = h2u(a);
}

template<bool ODD, bool FIRST>
__device__ __forceinline__ void do_sample_t(int2 sh, uint4 wv,
                                            int wp, int hbase,
                                            const char* __restrict__ planeB,
                                            unsigned hacc[KH_][2])
{
    const __half2 w00 = u2h(wv.x), w01 = u2h(wv.y), w10 = u2h(wv.z), w11 = u2h(wv.w);
    const int cl = wp + sh.y;
    const int y0 = hbase + sh.x;
    const int c2 = ODD ? cl + 1 : cl + 2;           // second-load column
    const bool v1 = (unsigned)cl < (unsigned)W_;    // pair-atomic / single col
    const bool v2 = (unsigned)c2 < (unsigned)W_;
    const char* __restrict__ zp = (const char*)g_zero;

    if (y0 >= 0 && y0 <= H_ - (KH_ + 1)) {          // warp-uniform fast path
        const char* p1 = v1 ? planeB + cl * 4 + y0 * ROW2_ : zp;
        const char* p2 = v2 ? planeB + c2 * 4 + y0 * ROW2_ : zp;
        Row3 P = ldRow<ODD>(p1, p2);
        #pragma unroll
        for (int r = 1; r <= KH_; r++) {
            Row3 C = ldRow<ODD>(p1 + r * ROW2_, p2 + r * ROW2_);
            tap_row<FIRST>(P, C, hacc[r-1][0], hacc[r-1][1], w00, w01, w10, w11);
            P = C;
        }
    } else {                                         // edge windows
        const char* p1 = (v1 && (unsigned)y0 < (unsigned)H_) ? planeB + cl * 4 + y0 * ROW2_ : zp;
        const char* p2 = (v2 && (unsigned)y0 < (unsigned)H_) ? planeB + c2 * 4 + y0 * ROW2_ : zp;
        Row3 P = ldRow<ODD>(p1, p2);
        #pragma unroll
        for (int r = 1; r <= KH_; r++) {
            int y = y0 + r;
            bool yv = (unsigned)y < (unsigned)H_;
            const char* q1 = (v1 && yv) ? planeB + cl * 4 + y * ROW2_ : zp;
            const char* q2 = (v2 && yv) ? planeB + c2 * 4 + y * ROW2_ : zp;
            Row3 C = ldRow<ODD>(q1, q2);
            tap_row<FIRST>(P, C, hacc[r-1][0], hacc[r-1][1], w00, w01, w10, w11);
            P = C;
        }
    }
}

template<bool FIRST>
__device__ __forceinline__ void do_sample(int s, const int2* s_sh, const uint4* s_w,
                                          int wp, int hbase,
                                          const char* __restrict__ planeB,
                                          unsigned hacc[KH_][2])
{
    const int2  sh = s_sh[s];
    const uint4 wv = s_w[s];
    if (sh.y & 1) do_sample_t<true,  FIRST>(sh, wv, wp, hbase, planeB, hacc);
    else          do_sample_t<false, FIRST>(sh, wv, wp, hbase, planeB, hacc);
}

__global__ void __launch_bounds__(128, 7) disp_kernel(float* __restrict__ out)
{
    __shared__ int2  s_sh[S_];
    __shared__ uint4 s_w[S_];
    const int tid = threadIdx.x;
    const int o = blockIdx.y, b = blockIdx.z;
    const int bo = b * O_ + o;
    if (tid < S_) { s_sh[tid] = g_shift[o * S_ + tid]; s_w[tid] = g_wtsh[o * S_ + tid]; }
    __syncthreads();

    const int lane = tid & 31, warp = tid >> 5;
    const int wblk = blockIdx.x & 1;
    const int cp   = (blockIdx.x >> 1) & 1;
    const int hblk = blockIdx.x >> 2;
    const int hbase = hblk * 32 + warp * KH_;
    const int wp = wblk * 64 + lane * 2;
    const char* __restrict__ planeB =
        (const char*)g_xP + ((size_t)bo * 2 + cp) * HW_ * 4;

    ull facc[KH_][2];
    #pragma unroll
    for (int i = 0; i < KH_; i++) { facc[i][0] = 0ull; facc[i][1] = 0ull; }

    #pragma unroll 1
    for (int sp = 0; sp < S_; sp += 4) {
        unsigned hacc[KH_][2];
        do_sample<true >(sp,     s_sh, s_w, wp, hbase, planeB, hacc);
        do_sample<false>(sp + 1, s_sh, s_w, wp, hbase, planeB, hacc);
        do_sample<false>(sp + 2, s_sh, s_w, wp, hbase, planeB, hacc);
        do_sample<false>(sp + 3, s_sh, s_w, wp, hbase, planeB, hacc);
        #pragma unroll
        for (int kh = 0; kh < KH_; kh++) {
            add2(facc[kh][0], h2f2(hacc[kh][0]));
            add2(facc[kh][1], h2f2(hacc[kh][1]));
        }
    }

    float* __restrict__ ob = out + ((size_t)bo * CPO_ + 2 * cp) * HW_;
    #pragma unroll
    for (int kh = 0; kh < KH_; kh++) {
        const int h = hbase + kh;
        float a0, a1, b0, b1;
        unpk(facc[kh][0], a0, a1);   // pixel wp:   ch lo, hi
        unpk(facc[kh][1], b0, b1);   // pixel wp+1: ch lo, hi
        *reinterpret_cast<float2*>(ob + (size_t)h * W_ + wp)       = make_float2(a0, b0);
        *reinterpret_cast<float2*>(ob + HW_ + (size_t)h * W_ + wp) = make_float2(a1, b1);
    }
}

extern "C" void kernel_launch(void* const* d_in, const int* in_sizes, int n_in,
                              void* d_out, int out_size)
{
    const float* x  = (const float*)d_in[0];
    const float* ox = (const float*)d_in[1];
    const float* oy = (const float*)d_in[2];
    const float* ua = (const float*)d_in[3];
    const float* us = (const float*)d_in[4];
    const float* ar = (const float*)d_in[5];
    const float* sr = (const float*)d_in[6];
    float* out = (float*)d_out;

    pre_kernel<<<NT_ + O_/8, 256>>>(x, ox, oy, ua, us, ar, sr);
    disp_kernel<<<dim3((H_/32) * 2 * 2, O_, B_), 128>>>(out);
}